// round 6
// baseline (speedup 1.0000x reference)
#include <cuda_runtime.h>
#include <cstdint>

// ---------------------------------------------------------------------------
// Noise2Void masked-MSE, exact replication of the JAX reference with
// jax.random.key(42) under the PARTITIONABLE threefry scheme (JAX >= 0.5
// default: jax_threefry_partitionable=True).
//
// Loss collapses to hot pixels only:
//   loss = sum_t (x[n,c,ry,rx] - x[n,c,hy,hx])^2 / (N*C*K)
//
// Partitionable RNG:
//   split(key,2)[i]      = full block threefry(key; x0=0, x1=i)
//   random_bits32(key)[i] = o0 ^ o1 of threefry(key; x0=0, x1=i)
//   randint(k,0,32)      = lower_bits % 32, lower_bits from SECOND foldlike
//                          sub-key (span=32 => multiplier term vanishes)
//   uniform(k)[i]        = bitcast((bits>>9)|0x3f800000) - 1
// ---------------------------------------------------------------------------

#define N_  32
#define C_  3
#define H_  512
#define W_  512
#define K_  256           // hot pixels per (n,c) = 16*16
#define ITEMS 24576       // N_*C_*K_
#define TPB  256
#define NBLK 96           // ITEMS / TPB

__device__ float g_partial[NBLK];

__host__ __device__ __forceinline__ void threefry2x32(
    uint32_t k0, uint32_t k1, uint32_t x0, uint32_t x1,
    uint32_t &o0, uint32_t &o1)
{
    const uint32_t ks0 = k0, ks1 = k1, ks2 = k0 ^ k1 ^ 0x1BD11BDAu;
    x0 += ks0; x1 += ks1;
#define TF_R4(a,b,c,d)                                           \
    x0 += x1; x1 = (x1<<(a))|(x1>>(32-(a))); x1 ^= x0;           \
    x0 += x1; x1 = (x1<<(b))|(x1>>(32-(b))); x1 ^= x0;           \
    x0 += x1; x1 = (x1<<(c))|(x1>>(32-(c))); x1 ^= x0;           \
    x0 += x1; x1 = (x1<<(d))|(x1>>(32-(d))); x1 ^= x0;
    TF_R4(13,15,26, 6)  x0 += ks1; x1 += ks2 + 1u;
    TF_R4(17,29,16,24)  x0 += ks2; x1 += ks0 + 2u;
    TF_R4(13,15,26, 6)  x0 += ks0; x1 += ks1 + 3u;
    TF_R4(17,29,16,24)  x0 += ks1; x1 += ks2 + 4u;
    TF_R4(13,15,26, 6)  x0 += ks2; x1 += ks0 + 5u;
#undef TF_R4
    o0 = x0; o1 = x1;
}

// partitionable random_bits: 32-bit element i = o0 ^ o1 of block (0, i)
__device__ __forceinline__ uint32_t rb32(uint32_t k0, uint32_t k1, uint32_t i)
{
    uint32_t o0, o1;
    threefry2x32(k0, k1, 0u, i, o0, o1);
    return o0 ^ o1;
}

__global__ void __launch_bounds__(TPB)
n2v_main(const float* __restrict__ x,
         uint32_t kl0, uint32_t kl1,   // randint lower-bits key
         uint32_t ku0, uint32_t ku1)   // uniform key (k2)
{
    int t = blockIdx.x * TPB + threadIdx.x;   // item index in [0, ITEMS)

    // off tensor shape (N,C,16,16,2): flat index 2t -> y offset, 2t+1 -> x.
    uint32_t oy = rb32(kl0, kl1, (uint32_t)(2 * t));
    uint32_t ox = rb32(kl0, kl1, (uint32_t)(2 * t + 1));
    uint32_t ub = rb32(ku0, ku1, (uint32_t)t);

    int nc = t >> 8;            // n*C + c
    int k  = t & 255;
    int by = k >> 4;
    int bx = k & 15;

    int hy = by * 32 + (int)(oy & 31u);
    int hx = bx * 32 + (int)(ox & 31u);

    // ROI bounds, faithful quirk: roimax = min(hc+3, shape-1)
    int rmin0 = max(hy - 2, 0);
    int rmax0 = min(hy + 3, H_ - 1);
    int rmin1 = max(hx - 2, 0);
    int rmax1 = min(hx + 3, W_ - 1);
    int sh0 = rmax0 - rmin0;
    int sh1 = rmax1 - rmin1;

    bool hasc = (sh0 > 2) && (sh1 > 2);
    int m = sh0 * sh1 - (hasc ? 1 : 0);

    // uniform in [0,1): bitcast((bits>>9)|0x3f800000) - 1.0
    float uf = __uint_as_float((ub >> 9) | 0x3f800000u) - 1.0f;
    int u = (int)floorf(uf * (float)m);
    u = min(u, m - 1);
    int cflat = 2 * sh1 + 2;                 // flat index of rc=(2,2)
    if (hasc && u >= cflat) u += 1;

    int ry = rmin0 + u / sh1;
    int rx = rmin1 + u % sh1;

    const float* img = x + (size_t)nc * (H_ * W_);
    float a = __ldg(img + ry * W_ + rx);
    float b = __ldg(img + hy * W_ + hx);
    float d = a - b;
    float acc = d * d;

    // block reduction
    __shared__ float sred[TPB];
    sred[threadIdx.x] = acc;
    __syncthreads();
#pragma unroll
    for (int s = TPB / 2; s > 0; s >>= 1) {
        if (threadIdx.x < s) sred[threadIdx.x] += sred[threadIdx.x + s];
        __syncthreads();
    }
    if (threadIdx.x == 0) g_partial[blockIdx.x] = sred[0];
}

__global__ void n2v_finalize(float* __restrict__ out)
{
    int t = threadIdx.x;                 // 128 threads
    float v = (t < NBLK) ? g_partial[t] : 0.0f;
#pragma unroll
    for (int o = 16; o > 0; o >>= 1)
        v += __shfl_down_sync(0xFFFFFFFFu, v, o);
    __shared__ float w[4];
    if ((t & 31) == 0) w[t >> 5] = v;
    __syncthreads();
    if (t == 0)
        out[0] = (w[0] + w[1] + w[2] + w[3]) / 24576.0f;  // mask.sum() = N*C*K
}

extern "C" void kernel_launch(void* const* d_in, const int* in_sizes, int n_in,
                              void* d_out, int out_size)
{
    (void)in_sizes; (void)n_in; (void)out_size;
    const float* x = (const float*)d_in[0];
    float* out = (float*)d_out;

    // ---- Derive JAX keys on host (pure CPU math, graph-capture safe) ----
    // root = key(42) = (0, 42)
    uint32_t A0, A1, B0, B1;
    // split(root, 2) foldlike: sub-key i = full block threefry(root; 0, i)
    threefry2x32(0u, 42u, 0u, 0u, A0, A1);   // k1 (randint key)
    threefry2x32(0u, 42u, 0u, 1u, B0, B1);   // k2 (uniform key)

    // randint internally splits k1 (foldlike); lower_bits uses the SECOND
    // sub-key = threefry(k1; 0, 1)
    uint32_t kl0, kl1, dh0, dh1;
    threefry2x32(A0, A1, 0u, 0u, dh0, dh1);  // higher-bits key (unused: mult=0)
    threefry2x32(A0, A1, 0u, 1u, kl0, kl1);  // lower-bits key
    (void)dh0; (void)dh1;

    n2v_main<<<NBLK, TPB>>>(x, kl0, kl1, B0, B1);
    n2v_finalize<<<1, 128>>>(out);
}

// round 7
// speedup vs baseline: 1.3029x; 1.3029x over previous
#include <cuda_runtime.h>
#include <cstdint>

// ---------------------------------------------------------------------------
// Noise2Void masked-MSE, exact replication of the JAX reference with
// jax.random.key(42) under the PARTITIONABLE threefry scheme (JAX >= 0.5
// default: jax_threefry_partitionable=True).
//
// Loss collapses to hot pixels only:
//   loss = sum_t (x[n,c,ry,rx] - x[n,c,hy,hx])^2 / (N*C*K)
//
// Single fused kernel: per-block warp-shuffle reduction -> g_partial,
// last-block-done (threadfence + atomicInc) deterministic final reduce,
// counter self-resets so the launch is CUDA-graph-replay idempotent.
// ---------------------------------------------------------------------------

#define N_  32
#define C_  3
#define H_  512
#define W_  512
#define ITEMS 24576       // N_*C_*256
#define TPB  256
#define NBLK 96           // ITEMS / TPB

__device__ float g_partial[NBLK];
__device__ unsigned int g_count = 0;

__host__ __device__ __forceinline__ void threefry2x32(
    uint32_t k0, uint32_t k1, uint32_t x0, uint32_t x1,
    uint32_t &o0, uint32_t &o1)
{
    const uint32_t ks0 = k0, ks1 = k1, ks2 = k0 ^ k1 ^ 0x1BD11BDAu;
    x0 += ks0; x1 += ks1;
#define TF_R4(a,b,c,d)                                           \
    x0 += x1; x1 = (x1<<(a))|(x1>>(32-(a))); x1 ^= x0;           \
    x0 += x1; x1 = (x1<<(b))|(x1>>(32-(b))); x1 ^= x0;           \
    x0 += x1; x1 = (x1<<(c))|(x1>>(32-(c))); x1 ^= x0;           \
    x0 += x1; x1 = (x1<<(d))|(x1>>(32-(d))); x1 ^= x0;
    TF_R4(13,15,26, 6)  x0 += ks1; x1 += ks2 + 1u;
    TF_R4(17,29,16,24)  x0 += ks2; x1 += ks0 + 2u;
    TF_R4(13,15,26, 6)  x0 += ks0; x1 += ks1 + 3u;
    TF_R4(17,29,16,24)  x0 += ks1; x1 += ks2 + 4u;
    TF_R4(13,15,26, 6)  x0 += ks2; x1 += ks0 + 5u;
#undef TF_R4
    o0 = x0; o1 = x1;
}

// partitionable random_bits: 32-bit element i = o0 ^ o1 of block (0, i)
__device__ __forceinline__ uint32_t rb32(uint32_t k0, uint32_t k1, uint32_t i)
{
    uint32_t o0, o1;
    threefry2x32(k0, k1, 0u, i, o0, o1);
    return o0 ^ o1;
}

__device__ __forceinline__ float warp_sum(float v)
{
#pragma unroll
    for (int o = 16; o > 0; o >>= 1)
        v += __shfl_down_sync(0xFFFFFFFFu, v, o);
    return v;
}

__global__ void __launch_bounds__(TPB)
n2v_fused(const float* __restrict__ x, float* __restrict__ out,
          uint32_t kl0, uint32_t kl1,   // randint lower-bits key
          uint32_t ku0, uint32_t ku1)   // uniform key (k2)
{
    const int tid  = threadIdx.x;
    const int lane = tid & 31;
    const int wid  = tid >> 5;
    const int t    = blockIdx.x * TPB + tid;   // item index in [0, ITEMS)

    // off tensor shape (N,C,16,16,2): flat index 2t -> y offset, 2t+1 -> x.
    uint32_t oy = rb32(kl0, kl1, (uint32_t)(2 * t));
    uint32_t ox = rb32(kl0, kl1, (uint32_t)(2 * t + 1));
    uint32_t ub = rb32(ku0, ku1, (uint32_t)t);

    int nc = t >> 8;            // n*C + c
    int k  = t & 255;
    int by = k >> 4;
    int bx = k & 15;

    int hy = by * 32 + (int)(oy & 31u);
    int hx = bx * 32 + (int)(ox & 31u);

    // ROI bounds, faithful quirk: roimax = min(hc+3, shape-1)
    int rmin0 = max(hy - 2, 0);
    int rmax0 = min(hy + 3, H_ - 1);
    int rmin1 = max(hx - 2, 0);
    int rmax1 = min(hx + 3, W_ - 1);
    int sh0 = rmax0 - rmin0;
    int sh1 = rmax1 - rmin1;

    bool hasc = (sh0 > 2) && (sh1 > 2);
    int m = sh0 * sh1 - (hasc ? 1 : 0);

    // uniform in [0,1): bitcast((bits>>9)|0x3f800000) - 1.0
    float uf = __uint_as_float((ub >> 9) | 0x3f800000u) - 1.0f;
    int u = (int)floorf(uf * (float)m);
    u = min(u, m - 1);
    int cflat = 2 * sh1 + 2;                 // flat index of rc=(2,2)
    if (hasc && u >= cflat) u += 1;

    int ry = rmin0 + u / sh1;
    int rx = rmin1 + u % sh1;

    const float* img = x + (size_t)nc * (H_ * W_);
    float a = __ldg(img + ry * W_ + rx);
    float b = __ldg(img + hy * W_ + hx);
    float d = a - b;

    // ---- block reduction (warp shuffles + one smem hop) ----
    float v = warp_sum(d * d);
    __shared__ float wsum[TPB / 32];
    if (lane == 0) wsum[wid] = v;
    __syncthreads();
    __shared__ bool is_last;
    if (tid == 0) {
        float s = 0.0f;
#pragma unroll
        for (int i = 0; i < TPB / 32; i++) s += wsum[i];
        g_partial[blockIdx.x] = s;
        __threadfence();
        unsigned int prev = atomicInc(&g_count, NBLK - 1);  // wraps to 0 at NBLK-1
        is_last = (prev == NBLK - 1);
    }
    __syncthreads();

    // ---- last block performs the deterministic final reduction ----
    if (is_last) {
        float p = (tid < NBLK) ? g_partial[tid] : 0.0f;   // 96 partials
        p = warp_sum(p);
        if (lane == 0) wsum[wid] = p;
        __syncthreads();
        if (tid == 0) {
            float s = wsum[0] + wsum[1] + wsum[2];        // blocks 0..95 live in warps 0..2
            out[0] = s / 24576.0f;                        // mask.sum() = N*C*K exactly
        }
    }
}

extern "C" void kernel_launch(void* const* d_in, const int* in_sizes, int n_in,
                              void* d_out, int out_size)
{
    (void)in_sizes; (void)n_in; (void)out_size;
    const float* x = (const float*)d_in[0];
    float* out = (float*)d_out;

    // ---- Derive JAX keys on host (pure CPU math, graph-capture safe) ----
    // root = key(42) = (0, 42)
    uint32_t A0, A1, B0, B1;
    // split(root, 2) foldlike: sub-key i = full block threefry(root; 0, i)
    threefry2x32(0u, 42u, 0u, 0u, A0, A1);   // k1 (randint key)
    threefry2x32(0u, 42u, 0u, 1u, B0, B1);   // k2 (uniform key)

    // randint internally splits k1 (foldlike); lower_bits uses the SECOND
    // sub-key = threefry(k1; 0, 1). (higher-bits key unused: (2^16 % 32)^2 % 32 = 0)
    uint32_t kl0, kl1;
    threefry2x32(A0, A1, 0u, 1u, kl0, kl1);

    n2v_fused<<<NBLK, TPB>>>(x, out, kl0, kl1, B0, B1);
}